// round 15
// baseline (speedup 1.0000x reference)
#include <cuda_runtime.h>
#include <cuda_fp16.h>
#include <cstdint>

#define N_NODES 100000
#define N_EDGES 1600000
#define IN_C 128
#define OUT_C 64
#define ROW_CAP 64   // padded CSR capacity; P(deg_in > 64) ~ 1e-30 at mean 16

// ------------------------- device scratch (no alloc allowed) ----------------
__device__ __half g_h16[N_NODES * OUT_C];          // 12.8 MB (L2-resident)
__device__ int    g_degs[2 * N_NODES];             // [0,N): deg_out  [N,2N): deg_in
__device__ int    g_esrc[N_NODES * ROW_CAP];       // 25.6 MB padded CSR

// ---------------------------------------------------------------------------
// deg_out (feeds gemm epilogue scaling)
// ---------------------------------------------------------------------------
__global__ __launch_bounds__(256) void degree_out_kernel(const int* __restrict__ src) {
    int i = blockIdx.x * blockDim.x + threadIdx.x;
    if (i < N_EDGES) atomicAdd(&g_degs[__ldcs(&src[i])], 1);
}

// ---------------------------------------------------------------------------
// fused count + fill: one pass builds degree AND padded CSR (no scan needed)
// ---------------------------------------------------------------------------
__global__ __launch_bounds__(256) void csr_fill_fused_kernel(const int* __restrict__ src,
                                                             const int* __restrict__ dst) {
    int i = blockIdx.x * blockDim.x + threadIdx.x;
    if (i < N_EDGES) {
        int s = __ldcs(&src[i]);
        int d = __ldcs(&dst[i]);
        int pos = atomicAdd(&g_degs[N_NODES + d], 1);
        g_esrc[(size_t)d * ROW_CAP + pos] = s;
    }
}

// ---------------------------------------------------------------------------
// GEMM via mma.sync (HMMA fp16 -> fp32 accum), norm_src in epilogue.
// (validated in R12)
// ---------------------------------------------------------------------------
__global__ __launch_bounds__(256) void mma_gemm_kernel(const float* __restrict__ x,
                                                       const float* __restrict__ w) {
    __shared__ __align__(16) __half xs[128][72];   // 18.4 KB (one 64-k chunk)
    __shared__ __align__(16) __half ws[128][72];   // 18.4 KB (all 128 k)

    const int t = threadIdx.x;
    const int lane = t & 31;
    const int wid = t >> 5;                 // 0..7
    const int nbase = blockIdx.x * 128;
    const int wb = wid * 16;                // warp's row base within block

    // stage W fully: 8192 floats -> fp16
    #pragma unroll
    for (int j = 0; j < 4; j++) {
        int g = t + 256 * j;                // 0..1023
        int k = g >> 3;
        int n8 = (g & 7) * 8;
        const float4* wp = (const float4*)&w[k * OUT_C + n8];
        float4 v0 = wp[0], v1 = wp[1];
        __half2 h0 = __floats2half2_rn(v0.x, v0.y);
        __half2 h1 = __floats2half2_rn(v0.z, v0.w);
        __half2 h2 = __floats2half2_rn(v1.x, v1.y);
        __half2 h3 = __floats2half2_rn(v1.z, v1.w);
        uint4 u;
        u.x = *(unsigned*)&h0; u.y = *(unsigned*)&h1;
        u.z = *(unsigned*)&h2; u.w = *(unsigned*)&h3;
        *(uint4*)&ws[k][n8] = u;
    }

    float d[8][4];
    #pragma unroll
    for (int i = 0; i < 8; i++)
        #pragma unroll
        for (int j = 0; j < 4; j++) d[i][j] = 0.0f;

    const int r_off = ((lane >> 3) & 1) * 8 + (lane & 7);   // row within 16
    const int c_off = ((lane >> 4) & 1) * 8;                // col half

    for (int kc = 0; kc < 2; kc++) {
        __syncthreads();
        // stage x chunk [128 rows][64 k]
        {
            int row = t & 127;
            int base = (t >> 7) * 32;            // 0 or 32
            int node = nbase + row;
            if (node < N_NODES) {
                const float4* xp = (const float4*)&x[(size_t)node * IN_C + kc * 64 + base];
                #pragma unroll
                for (int q = 0; q < 4; q++) {
                    float4 v0 = xp[2 * q];
                    float4 v1 = xp[2 * q + 1];
                    __half2 h0 = __floats2half2_rn(v0.x, v0.y);
                    __half2 h1 = __floats2half2_rn(v0.z, v0.w);
                    __half2 h2 = __floats2half2_rn(v1.x, v1.y);
                    __half2 h3 = __floats2half2_rn(v1.z, v1.w);
                    uint4 u;
                    u.x = *(unsigned*)&h0; u.y = *(unsigned*)&h1;
                    u.z = *(unsigned*)&h2; u.w = *(unsigned*)&h3;
                    *(uint4*)&xs[row][base + q * 8] = u;
                }
            } else {
                uint4 z = make_uint4(0, 0, 0, 0);
                #pragma unroll
                for (int q = 0; q < 4; q++)
                    *(uint4*)&xs[row][base + q * 8] = z;
            }
        }
        __syncthreads();

        #pragma unroll
        for (int kt = 0; kt < 4; kt++) {
            int k0s = kt * 16;                 // k within xs chunk
            int k0w = kc * 64 + kt * 16;       // k within ws (full)
            uint32_t a0, a1, a2, a3;
            uint32_t aaddr = (uint32_t)__cvta_generic_to_shared(&xs[wb + r_off][k0s + c_off]);
            asm volatile("ldmatrix.sync.aligned.m8n8.x4.shared.b16 {%0,%1,%2,%3}, [%4];"
                         : "=r"(a0), "=r"(a1), "=r"(a2), "=r"(a3) : "r"(aaddr));
            #pragma unroll
            for (int np = 0; np < 4; np++) {
                int n0 = np * 16;
                uint32_t b0, b1, b2, b3;
                uint32_t baddr = (uint32_t)__cvta_generic_to_shared(&ws[k0w + r_off][n0 + c_off]);
                asm volatile("ldmatrix.sync.aligned.m8n8.x4.trans.shared.b16 {%0,%1,%2,%3}, [%4];"
                             : "=r"(b0), "=r"(b1), "=r"(b2), "=r"(b3) : "r"(baddr));
                asm volatile("mma.sync.aligned.m16n8k16.row.col.f32.f16.f16.f32 "
                             "{%0,%1,%2,%3}, {%4,%5,%6,%7}, {%8,%9}, {%0,%1,%2,%3};"
                             : "+f"(d[np * 2][0]), "+f"(d[np * 2][1]),
                               "+f"(d[np * 2][2]), "+f"(d[np * 2][3])
                             : "r"(a0), "r"(a1), "r"(a2), "r"(a3), "r"(b0), "r"(b1));
                asm volatile("mma.sync.aligned.m16n8k16.row.col.f32.f16.f16.f32 "
                             "{%0,%1,%2,%3}, {%4,%5,%6,%7}, {%8,%9}, {%0,%1,%2,%3};"
                             : "+f"(d[np * 2 + 1][0]), "+f"(d[np * 2 + 1][1]),
                               "+f"(d[np * 2 + 1][2]), "+f"(d[np * 2 + 1][3])
                             : "r"(a0), "r"(a1), "r"(a2), "r"(a3), "r"(b2), "r"(b3));
            }
        }
    }

    // epilogue
    int r0 = nbase + wb + (lane >> 2);
    int r1 = r0 + 8;
    float rn0 = (r0 < N_NODES) ? rsqrtf(fmaxf((float)g_degs[r0], 1.0f)) : 0.0f;
    float rn1 = (r1 < N_NODES) ? rsqrtf(fmaxf((float)g_degs[r1], 1.0f)) : 0.0f;
    int c_base = (lane & 3) * 2;
    #pragma unroll
    for (int nt = 0; nt < 8; nt++) {
        int c = nt * 8 + c_base;
        if (r0 < N_NODES) {
            __half2 h = __floats2half2_rn(d[nt][0] * rn0, d[nt][1] * rn0);
            *(__half2*)&g_h16[(size_t)r0 * OUT_C + c] = h;
        }
        if (r1 < N_NODES) {
            __half2 h = __floats2half2_rn(d[nt][2] * rn1, d[nt][3] * rn1);
            *(__half2*)&g_h16[(size_t)r1 * OUT_C + c] = h;
        }
    }
}

// ---------------------------------------------------------------------------
// pull aggregation over padded CSR: 8 threads/node, uint4 (8-half) gathers.
// Halves the LDG count vs 16-thread/uint2 (the R14 binder was LSU issue).
// ---------------------------------------------------------------------------
__global__ __launch_bounds__(256) void aggregate_kernel(const float4* __restrict__ bias4,
                                                        float* __restrict__ out) {
    int gwarp = (blockIdx.x * 256 + threadIdx.x) >> 5;
    int lane  = threadIdx.x & 31;
    int node  = gwarp * 4 + (lane >> 3);     // 4 nodes per warp
    if (node >= N_NODES) return;
    int g = lane & 7;                        // col group of 8 halves

    int cnt = g_degs[N_NODES + node];
    const int* ep = &g_esrc[(size_t)node * ROW_CAP];

    float a0 = 0.f, a1 = 0.f, a2 = 0.f, a3 = 0.f;
    float a4 = 0.f, a5 = 0.f, a6 = 0.f, a7 = 0.f;

    int j = 0;
    for (; j + 4 <= cnt; j += 4) {
        uint4 r[4];
        #pragma unroll
        for (int q = 0; q < 4; q++) {
            int s = __ldcs(&ep[j + q]);
            r[q] = *(const uint4*)&g_h16[(size_t)s * OUT_C + g * 8];
        }
        #pragma unroll
        for (int q = 0; q < 4; q++) {
            float2 f0 = __half22float2(*(__half2*)&r[q].x);
            float2 f1 = __half22float2(*(__half2*)&r[q].y);
            float2 f2 = __half22float2(*(__half2*)&r[q].z);
            float2 f3 = __half22float2(*(__half2*)&r[q].w);
            a0 += f0.x; a1 += f0.y; a2 += f1.x; a3 += f1.y;
            a4 += f2.x; a5 += f2.y; a6 += f3.x; a7 += f3.y;
        }
    }
    for (; j < cnt; j++) {
        int s = __ldcs(&ep[j]);
        uint4 r = *(const uint4*)&g_h16[(size_t)s * OUT_C + g * 8];
        float2 f0 = __half22float2(*(__half2*)&r.x);
        float2 f1 = __half22float2(*(__half2*)&r.y);
        float2 f2 = __half22float2(*(__half2*)&r.z);
        float2 f3 = __half22float2(*(__half2*)&r.w);
        a0 += f0.x; a1 += f0.y; a2 += f1.x; a3 += f1.y;
        a4 += f2.x; a5 += f2.y; a6 += f3.x; a7 += f3.y;
    }

    float rn = rsqrtf(fmaxf((float)cnt, 1.0f));
    float4 b0 = bias4[g * 2];
    float4 b1 = bias4[g * 2 + 1];
    float4 r0, r1;
    r0.x = a0 * rn + b0.x; r0.y = a1 * rn + b0.y;
    r0.z = a2 * rn + b0.z; r0.w = a3 * rn + b0.w;
    r1.x = a4 * rn + b1.x; r1.y = a5 * rn + b1.y;
    r1.z = a6 * rn + b1.z; r1.w = a7 * rn + b1.w;
    float* op = &out[(size_t)node * OUT_C + g * 8];
    __stcs((float4*)op, r0);
    __stcs((float4*)(op + 4), r1);
}

// ---------------------------------------------------------------------------
extern "C" void kernel_launch(void* const* d_in, const int* in_sizes, int n_in,
                              void* d_out, int out_size) {
    const float* x      = (const float*)d_in[0];
    const float* weight = (const float*)d_in[1];
    const float* bias   = (const float*)d_in[2];
    const int*   src    = (const int*)d_in[3];
    const int*   dst    = (const int*)d_in[4];
    float* out = (float*)d_out;

    cudaStream_t s2;
    cudaEvent_t evFork, evFill;
    cudaStreamCreateWithFlags(&s2, cudaStreamNonBlocking);
    cudaEventCreateWithFlags(&evFork, cudaEventDisableTiming);
    cudaEventCreateWithFlags(&evFill, cudaEventDisableTiming);

    void* degs_ptr = nullptr;
    cudaGetSymbolAddress(&degs_ptr, g_degs);

    // fork from the origin (capture) stream FIRST
    cudaEventRecord(evFork, 0);
    cudaStreamWaitEvent(s2, evFork, 0);

    // ---- track B (s2): memset deg_in half -> fused count+fill (padded CSR)
    cudaMemsetAsync((char*)degs_ptr + N_NODES * sizeof(int), 0,
                    N_NODES * sizeof(int), s2);
    csr_fill_fused_kernel<<<(N_EDGES + 255) / 256, 256, 0, s2>>>(src, dst);
    cudaEventRecord(evFill, s2);

    // ---- track A (main): memset deg_out half -> deg_out -> HMMA gemm
    cudaMemsetAsync(degs_ptr, 0, N_NODES * sizeof(int));
    degree_out_kernel<<<(N_EDGES + 255) / 256, 256>>>(src);
    mma_gemm_kernel<<<(N_NODES + 127) / 128, 256>>>(x, weight);

    // join: aggregate needs h (main) + padded CSR (s2)
    cudaStreamWaitEvent(0, evFill, 0);
    int nwarps = (N_NODES + 3) / 4;
    aggregate_kernel<<<(nwarps + 7) / 8, 256>>>((const float4*)bias, out);

    cudaEventDestroy(evFork);
    cudaEventDestroy(evFill);
    cudaStreamDestroy(s2);
}

// round 16
// speedup vs baseline: 1.0112x; 1.0112x over previous
#include <cuda_runtime.h>
#include <cuda_fp16.h>
#include <cstdint>

#define N_NODES 100000
#define N_EDGES 1600000
#define IN_C 128
#define OUT_C 64
#define ROW_CAP 64   // padded CSR capacity; P(deg_in > 64) ~ 1e-30 at mean 16

// ------------------------- device scratch (no alloc allowed) ----------------
__device__ __half g_h16[N_NODES * OUT_C];          // 12.8 MB (L2-resident)
__device__ int    g_degs[2 * N_NODES];             // [0,N): deg_out  [N,2N): deg_in
__device__ int    g_esrc[N_NODES * ROW_CAP];       // 25.6 MB padded CSR

// ---------------------------------------------------------------------------
// deg_out (feeds gemm epilogue scaling)
// ---------------------------------------------------------------------------
__global__ __launch_bounds__(256) void degree_out_kernel(const int* __restrict__ src) {
    int i = blockIdx.x * blockDim.x + threadIdx.x;
    if (i < N_EDGES) atomicAdd(&g_degs[__ldcs(&src[i])], 1);
}

// ---------------------------------------------------------------------------
// fused count + fill: one pass builds degree AND padded CSR (no scan needed)
// ---------------------------------------------------------------------------
__global__ __launch_bounds__(256) void csr_fill_fused_kernel(const int* __restrict__ src,
                                                             const int* __restrict__ dst) {
    int i = blockIdx.x * blockDim.x + threadIdx.x;
    if (i < N_EDGES) {
        int s = __ldcs(&src[i]);
        int d = __ldcs(&dst[i]);
        int pos = atomicAdd(&g_degs[N_NODES + d], 1);
        g_esrc[(size_t)d * ROW_CAP + pos] = s;
    }
}

// ---------------------------------------------------------------------------
// GEMM via mma.sync (HMMA fp16 -> fp32 accum), norm_src in epilogue.
// + chunk-1 x prefetch (each thread's chunk-1 data = exactly one 128B line)
// ---------------------------------------------------------------------------
__global__ __launch_bounds__(256) void mma_gemm_kernel(const float* __restrict__ x,
                                                       const float* __restrict__ w) {
    __shared__ __align__(16) __half xs[128][72];   // 18.4 KB (one 64-k chunk)
    __shared__ __align__(16) __half ws[128][72];   // 18.4 KB (all 128 k)

    const int t = threadIdx.x;
    const int lane = t & 31;
    const int wid = t >> 5;                 // 0..7
    const int nbase = blockIdx.x * 128;
    const int wb = wid * 16;                // warp's row base within block

    // prefetch chunk-1 x line (overlaps W staging + chunk-0 load + compute)
    {
        int row = t & 127;
        int base = (t >> 7) * 32;
        int node = nbase + row;
        if (node < N_NODES)
            asm volatile("prefetch.global.L1 [%0];"
                         :: "l"(&x[(size_t)node * IN_C + 64 + base]));
    }

    // stage W fully: 8192 floats -> fp16
    #pragma unroll
    for (int j = 0; j < 4; j++) {
        int g = t + 256 * j;                // 0..1023
        int k = g >> 3;
        int n8 = (g & 7) * 8;
        const float4* wp = (const float4*)&w[k * OUT_C + n8];
        float4 v0 = wp[0], v1 = wp[1];
        __half2 h0 = __floats2half2_rn(v0.x, v0.y);
        __half2 h1 = __floats2half2_rn(v0.z, v0.w);
        __half2 h2 = __floats2half2_rn(v1.x, v1.y);
        __half2 h3 = __floats2half2_rn(v1.z, v1.w);
        uint4 u;
        u.x = *(unsigned*)&h0; u.y = *(unsigned*)&h1;
        u.z = *(unsigned*)&h2; u.w = *(unsigned*)&h3;
        *(uint4*)&ws[k][n8] = u;
    }

    float d[8][4];
    #pragma unroll
    for (int i = 0; i < 8; i++)
        #pragma unroll
        for (int j = 0; j < 4; j++) d[i][j] = 0.0f;

    const int r_off = ((lane >> 3) & 1) * 8 + (lane & 7);   // row within 16
    const int c_off = ((lane >> 4) & 1) * 8;                // col half

    for (int kc = 0; kc < 2; kc++) {
        __syncthreads();
        // stage x chunk [128 rows][64 k]
        {
            int row = t & 127;
            int base = (t >> 7) * 32;            // 0 or 32
            int node = nbase + row;
            if (node < N_NODES) {
                const float4* xp = (const float4*)&x[(size_t)node * IN_C + kc * 64 + base];
                #pragma unroll
                for (int q = 0; q < 4; q++) {
                    float4 v0 = xp[2 * q];
                    float4 v1 = xp[2 * q + 1];
                    __half2 h0 = __floats2half2_rn(v0.x, v0.y);
                    __half2 h1 = __floats2half2_rn(v0.z, v0.w);
                    __half2 h2 = __floats2half2_rn(v1.x, v1.y);
                    __half2 h3 = __floats2half2_rn(v1.z, v1.w);
                    uint4 u;
                    u.x = *(unsigned*)&h0; u.y = *(unsigned*)&h1;
                    u.z = *(unsigned*)&h2; u.w = *(unsigned*)&h3;
                    *(uint4*)&xs[row][base + q * 8] = u;
                }
            } else {
                uint4 z = make_uint4(0, 0, 0, 0);
                #pragma unroll
                for (int q = 0; q < 4; q++)
                    *(uint4*)&xs[row][base + q * 8] = z;
            }
        }
        __syncthreads();

        #pragma unroll
        for (int kt = 0; kt < 4; kt++) {
            int k0s = kt * 16;                 // k within xs chunk
            int k0w = kc * 64 + kt * 16;       // k within ws (full)
            uint32_t a0, a1, a2, a3;
            uint32_t aaddr = (uint32_t)__cvta_generic_to_shared(&xs[wb + r_off][k0s + c_off]);
            asm volatile("ldmatrix.sync.aligned.m8n8.x4.shared.b16 {%0,%1,%2,%3}, [%4];"
                         : "=r"(a0), "=r"(a1), "=r"(a2), "=r"(a3) : "r"(aaddr));
            #pragma unroll
            for (int np = 0; np < 4; np++) {
                int n0 = np * 16;
                uint32_t b0, b1, b2, b3;
                uint32_t baddr = (uint32_t)__cvta_generic_to_shared(&ws[k0w + r_off][n0 + c_off]);
                asm volatile("ldmatrix.sync.aligned.m8n8.x4.trans.shared.b16 {%0,%1,%2,%3}, [%4];"
                             : "=r"(b0), "=r"(b1), "=r"(b2), "=r"(b3) : "r"(baddr));
                asm volatile("mma.sync.aligned.m16n8k16.row.col.f32.f16.f16.f32 "
                             "{%0,%1,%2,%3}, {%4,%5,%6,%7}, {%8,%9}, {%0,%1,%2,%3};"
                             : "+f"(d[np * 2][0]), "+f"(d[np * 2][1]),
                               "+f"(d[np * 2][2]), "+f"(d[np * 2][3])
                             : "r"(a0), "r"(a1), "r"(a2), "r"(a3), "r"(b0), "r"(b1));
                asm volatile("mma.sync.aligned.m16n8k16.row.col.f32.f16.f16.f32 "
                             "{%0,%1,%2,%3}, {%4,%5,%6,%7}, {%8,%9}, {%0,%1,%2,%3};"
                             : "+f"(d[np * 2 + 1][0]), "+f"(d[np * 2 + 1][1]),
                               "+f"(d[np * 2 + 1][2]), "+f"(d[np * 2 + 1][3])
                             : "r"(a0), "r"(a1), "r"(a2), "r"(a3), "r"(b2), "r"(b3));
            }
        }
    }

    // epilogue
    int r0 = nbase + wb + (lane >> 2);
    int r1 = r0 + 8;
    float rn0 = (r0 < N_NODES) ? rsqrtf(fmaxf((float)g_degs[r0], 1.0f)) : 0.0f;
    float rn1 = (r1 < N_NODES) ? rsqrtf(fmaxf((float)g_degs[r1], 1.0f)) : 0.0f;
    int c_base = (lane & 3) * 2;
    #pragma unroll
    for (int nt = 0; nt < 8; nt++) {
        int c = nt * 8 + c_base;
        if (r0 < N_NODES) {
            __half2 h = __floats2half2_rn(d[nt][0] * rn0, d[nt][1] * rn0);
            *(__half2*)&g_h16[(size_t)r0 * OUT_C + c] = h;
        }
        if (r1 < N_NODES) {
            __half2 h = __floats2half2_rn(d[nt][2] * rn1, d[nt][3] * rn1);
            *(__half2*)&g_h16[(size_t)r1 * OUT_C + c] = h;
        }
    }
}

// ---------------------------------------------------------------------------
// pull aggregation: 8 threads/node, uint4 gathers, PAIRWISE fp16 pre-add
// (halves the cvt+FADD stream; pair-sums then accumulated in fp32).
// ---------------------------------------------------------------------------
__global__ __launch_bounds__(256) void aggregate_kernel(const float4* __restrict__ bias4,
                                                        float* __restrict__ out) {
    int gwarp = (blockIdx.x * 256 + threadIdx.x) >> 5;
    int lane  = threadIdx.x & 31;
    int node  = gwarp * 4 + (lane >> 3);     // 4 nodes per warp
    if (node >= N_NODES) return;
    int g = lane & 7;                        // col group of 8 halves

    int cnt = g_degs[N_NODES + node];
    const int* ep = &g_esrc[(size_t)node * ROW_CAP];

    float a0 = 0.f, a1 = 0.f, a2 = 0.f, a3 = 0.f;
    float a4 = 0.f, a5 = 0.f, a6 = 0.f, a7 = 0.f;

    int j = 0;
    for (; j + 4 <= cnt; j += 4) {
        uint4 r[4];
        #pragma unroll
        for (int q = 0; q < 4; q++) {
            int s = __ldcs(&ep[j + q]);
            r[q] = *(const uint4*)&g_h16[(size_t)s * OUT_C + g * 8];
        }
        // pairwise fp16 adds: (r0+r1), (r2+r3)
        __half2* h0 = (__half2*)&r[0];
        __half2* h1 = (__half2*)&r[1];
        __half2* h2 = (__half2*)&r[2];
        __half2* h3 = (__half2*)&r[3];
        __half2 pA[4], pB[4];
        #pragma unroll
        for (int k = 0; k < 4; k++) {
            pA[k] = __hadd2(h0[k], h1[k]);
            pB[k] = __hadd2(h2[k], h3[k]);
        }
        #pragma unroll
        for (int k = 0; k < 2; k++) {
            __half2* p = k ? pB : pA;
            float2 f0 = __half22float2(p[0]);
            float2 f1 = __half22float2(p[1]);
            float2 f2 = __half22float2(p[2]);
            float2 f3 = __half22float2(p[3]);
            a0 += f0.x; a1 += f0.y; a2 += f1.x; a3 += f1.y;
            a4 += f2.x; a5 += f2.y; a6 += f3.x; a7 += f3.y;
        }
    }
    for (; j < cnt; j++) {
        int s = __ldcs(&ep[j]);
        uint4 r = *(const uint4*)&g_h16[(size_t)s * OUT_C + g * 8];
        float2 f0 = __half22float2(*(__half2*)&r.x);
        float2 f1 = __half22float2(*(__half2*)&r.y);
        float2 f2 = __half22float2(*(__half2*)&r.z);
        float2 f3 = __half22float2(*(__half2*)&r.w);
        a0 += f0.x; a1 += f0.y; a2 += f1.x; a3 += f1.y;
        a4 += f2.x; a5 += f2.y; a6 += f3.x; a7 += f3.y;
    }

    float rn = rsqrtf(fmaxf((float)cnt, 1.0f));
    float4 b0 = bias4[g * 2];
    float4 b1 = bias4[g * 2 + 1];
    float4 r0, r1;
    r0.x = a0 * rn + b0.x; r0.y = a1 * rn + b0.y;
    r0.z = a2 * rn + b0.z; r0.w = a3 * rn + b0.w;
    r1.x = a4 * rn + b1.x; r1.y = a5 * rn + b1.y;
    r1.z = a6 * rn + b1.z; r1.w = a7 * rn + b1.w;
    float* op = &out[(size_t)node * OUT_C + g * 8];
    __stcs((float4*)op, r0);
    __stcs((float4*)(op + 4), r1);
}

// ---------------------------------------------------------------------------
extern "C" void kernel_launch(void* const* d_in, const int* in_sizes, int n_in,
                              void* d_out, int out_size) {
    const float* x      = (const float*)d_in[0];
    const float* weight = (const float*)d_in[1];
    const float* bias   = (const float*)d_in[2];
    const int*   src    = (const int*)d_in[3];
    const int*   dst    = (const int*)d_in[4];
    float* out = (float*)d_out;

    cudaStream_t s2;
    cudaEvent_t evFork, evFill;
    cudaStreamCreateWithFlags(&s2, cudaStreamNonBlocking);
    cudaEventCreateWithFlags(&evFork, cudaEventDisableTiming);
    cudaEventCreateWithFlags(&evFill, cudaEventDisableTiming);

    void* degs_ptr = nullptr;
    cudaGetSymbolAddress(&degs_ptr, g_degs);

    // fork from the origin (capture) stream FIRST
    cudaEventRecord(evFork, 0);
    cudaStreamWaitEvent(s2, evFork, 0);

    // ---- track B (s2): memset deg_in half -> fused count+fill (padded CSR)
    cudaMemsetAsync((char*)degs_ptr + N_NODES * sizeof(int), 0,
                    N_NODES * sizeof(int), s2);
    csr_fill_fused_kernel<<<(N_EDGES + 255) / 256, 256, 0, s2>>>(src, dst);
    cudaEventRecord(evFill, s2);

    // ---- track A (main): memset deg_out half -> deg_out -> HMMA gemm
    cudaMemsetAsync(degs_ptr, 0, N_NODES * sizeof(int));
    degree_out_kernel<<<(N_EDGES + 255) / 256, 256>>>(src);
    mma_gemm_kernel<<<(N_NODES + 127) / 128, 256>>>(x, weight);

    // join: aggregate needs h (main) + padded CSR (s2)
    cudaStreamWaitEvent(0, evFill, 0);
    int nwarps = (N_NODES + 3) / 4;
    aggregate_kernel<<<(nwarps + 7) / 8, 256>>>((const float4*)bias, out);

    cudaEventDestroy(evFork);
    cudaEventDestroy(evFill);
    cudaStreamDestroy(s2);
}

// round 17
// speedup vs baseline: 1.0566x; 1.0448x over previous
#include <cuda_runtime.h>
#include <cuda_fp16.h>
#include <cstdint>

#define N_NODES 100000
#define N_EDGES 1600000
#define IN_C 128
#define OUT_C 64
#define ROW_CAP 64   // padded CSR capacity; P(deg_in > 64) ~ 1e-30 at mean 16

// ------------------------- device scratch (no alloc allowed) ----------------
// NOTE: g_degs starts zero (module load) and is re-zeroed by aggregate_kernel
// at the end of every run -> no memset nodes needed, graph stays 4 kernels.
__device__ __half g_h16[N_NODES * OUT_C];          // 12.8 MB (L2-resident)
__device__ int    g_degs[2 * N_NODES];             // [0,N): deg_out  [N,2N): deg_in
__device__ int    g_esrc[N_NODES * ROW_CAP];       // 25.6 MB padded CSR

// ---------------------------------------------------------------------------
// deg_out (feeds gemm epilogue scaling)
// ---------------------------------------------------------------------------
__global__ __launch_bounds__(256) void degree_out_kernel(const int* __restrict__ src) {
    int i = blockIdx.x * blockDim.x + threadIdx.x;
    if (i < N_EDGES) atomicAdd(&g_degs[__ldcs(&src[i])], 1);
}

// ---------------------------------------------------------------------------
// fused count + fill: one pass builds deg_in AND padded CSR (no scan needed)
// ---------------------------------------------------------------------------
__global__ __launch_bounds__(256) void csr_fill_fused_kernel(const int* __restrict__ src,
                                                             const int* __restrict__ dst) {
    int i = blockIdx.x * blockDim.x + threadIdx.x;
    if (i < N_EDGES) {
        int s = __ldcs(&src[i]);
        int d = __ldcs(&dst[i]);
        int pos = atomicAdd(&g_degs[N_NODES + d], 1);
        g_esrc[(size_t)d * ROW_CAP + pos] = s;
    }
}

// ---------------------------------------------------------------------------
// GEMM via mma.sync (HMMA fp16 -> fp32 accum), norm_src in epilogue.
// ---------------------------------------------------------------------------
__global__ __launch_bounds__(256) void mma_gemm_kernel(const float* __restrict__ x,
                                                       const float* __restrict__ w) {
    __shared__ __align__(16) __half xs[128][72];   // 18.4 KB (one 64-k chunk)
    __shared__ __align__(16) __half ws[128][72];   // 18.4 KB (all 128 k)

    const int t = threadIdx.x;
    const int lane = t & 31;
    const int wid = t >> 5;                 // 0..7
    const int nbase = blockIdx.x * 128;
    const int wb = wid * 16;                // warp's row base within block

    // prefetch chunk-1 x line (overlaps W staging + chunk-0 load + compute)
    {
        int row = t & 127;
        int base = (t >> 7) * 32;
        int node = nbase + row;
        if (node < N_NODES)
            asm volatile("prefetch.global.L1 [%0];"
                         :: "l"(&x[(size_t)node * IN_C + 64 + base]));
    }

    // stage W fully: 8192 floats -> fp16
    #pragma unroll
    for (int j = 0; j < 4; j++) {
        int g = t + 256 * j;                // 0..1023
        int k = g >> 3;
        int n8 = (g & 7) * 8;
        const float4* wp = (const float4*)&w[k * OUT_C + n8];
        float4 v0 = wp[0], v1 = wp[1];
        __half2 h0 = __floats2half2_rn(v0.x, v0.y);
        __half2 h1 = __floats2half2_rn(v0.z, v0.w);
        __half2 h2 = __floats2half2_rn(v1.x, v1.y);
        __half2 h3 = __floats2half2_rn(v1.z, v1.w);
        uint4 u;
        u.x = *(unsigned*)&h0; u.y = *(unsigned*)&h1;
        u.z = *(unsigned*)&h2; u.w = *(unsigned*)&h3;
        *(uint4*)&ws[k][n8] = u;
    }

    float d[8][4];
    #pragma unroll
    for (int i = 0; i < 8; i++)
        #pragma unroll
        for (int j = 0; j < 4; j++) d[i][j] = 0.0f;

    const int r_off = ((lane >> 3) & 1) * 8 + (lane & 7);   // row within 16
    const int c_off = ((lane >> 4) & 1) * 8;                // col half

    for (int kc = 0; kc < 2; kc++) {
        __syncthreads();
        // stage x chunk [128 rows][64 k]
        {
            int row = t & 127;
            int base = (t >> 7) * 32;            // 0 or 32
            int node = nbase + row;
            if (node < N_NODES) {
                const float4* xp = (const float4*)&x[(size_t)node * IN_C + kc * 64 + base];
                #pragma unroll
                for (int q = 0; q < 4; q++) {
                    float4 v0 = xp[2 * q];
                    float4 v1 = xp[2 * q + 1];
                    __half2 h0 = __floats2half2_rn(v0.x, v0.y);
                    __half2 h1 = __floats2half2_rn(v0.z, v0.w);
                    __half2 h2 = __floats2half2_rn(v1.x, v1.y);
                    __half2 h3 = __floats2half2_rn(v1.z, v1.w);
                    uint4 u;
                    u.x = *(unsigned*)&h0; u.y = *(unsigned*)&h1;
                    u.z = *(unsigned*)&h2; u.w = *(unsigned*)&h3;
                    *(uint4*)&xs[row][base + q * 8] = u;
                }
            } else {
                uint4 z = make_uint4(0, 0, 0, 0);
                #pragma unroll
                for (int q = 0; q < 4; q++)
                    *(uint4*)&xs[row][base + q * 8] = z;
            }
        }
        __syncthreads();

        #pragma unroll
        for (int kt = 0; kt < 4; kt++) {
            int k0s = kt * 16;                 // k within xs chunk
            int k0w = kc * 64 + kt * 16;       // k within ws (full)
            uint32_t a0, a1, a2, a3;
            uint32_t aaddr = (uint32_t)__cvta_generic_to_shared(&xs[wb + r_off][k0s + c_off]);
            asm volatile("ldmatrix.sync.aligned.m8n8.x4.shared.b16 {%0,%1,%2,%3}, [%4];"
                         : "=r"(a0), "=r"(a1), "=r"(a2), "=r"(a3) : "r"(aaddr));
            #pragma unroll
            for (int np = 0; np < 4; np++) {
                int n0 = np * 16;
                uint32_t b0, b1, b2, b3;
                uint32_t baddr = (uint32_t)__cvta_generic_to_shared(&ws[k0w + r_off][n0 + c_off]);
                asm volatile("ldmatrix.sync.aligned.m8n8.x4.trans.shared.b16 {%0,%1,%2,%3}, [%4];"
                             : "=r"(b0), "=r"(b1), "=r"(b2), "=r"(b3) : "r"(baddr));
                asm volatile("mma.sync.aligned.m16n8k16.row.col.f32.f16.f16.f32 "
                             "{%0,%1,%2,%3}, {%4,%5,%6,%7}, {%8,%9}, {%0,%1,%2,%3};"
                             : "+f"(d[np * 2][0]), "+f"(d[np * 2][1]),
                               "+f"(d[np * 2][2]), "+f"(d[np * 2][3])
                             : "r"(a0), "r"(a1), "r"(a2), "r"(a3), "r"(b0), "r"(b1));
                asm volatile("mma.sync.aligned.m16n8k16.row.col.f32.f16.f16.f32 "
                             "{%0,%1,%2,%3}, {%4,%5,%6,%7}, {%8,%9}, {%0,%1,%2,%3};"
                             : "+f"(d[np * 2 + 1][0]), "+f"(d[np * 2 + 1][1]),
                               "+f"(d[np * 2 + 1][2]), "+f"(d[np * 2 + 1][3])
                             : "r"(a0), "r"(a1), "r"(a2), "r"(a3), "r"(b2), "r"(b3));
            }
        }
    }

    // epilogue
    int r0 = nbase + wb + (lane >> 2);
    int r1 = r0 + 8;
    float rn0 = (r0 < N_NODES) ? rsqrtf(fmaxf((float)g_degs[r0], 1.0f)) : 0.0f;
    float rn1 = (r1 < N_NODES) ? rsqrtf(fmaxf((float)g_degs[r1], 1.0f)) : 0.0f;
    int c_base = (lane & 3) * 2;
    #pragma unroll
    for (int nt = 0; nt < 8; nt++) {
        int c = nt * 8 + c_base;
        if (r0 < N_NODES) {
            __half2 h = __floats2half2_rn(d[nt][0] * rn0, d[nt][1] * rn0);
            *(__half2*)&g_h16[(size_t)r0 * OUT_C + c] = h;
        }
        if (r1 < N_NODES) {
            __half2 h = __floats2half2_rn(d[nt][2] * rn1, d[nt][3] * rn1);
            *(__half2*)&g_h16[(size_t)r1 * OUT_C + c] = h;
        }
    }
}

// ---------------------------------------------------------------------------
// pull aggregation: 8 threads/node, uint4 gathers, 8-deep MLP, pairwise fp16
// pre-add. Ends by zeroing this node's degree counters (replay determinism).
// Grid is exactly 25000 full warps (100000 nodes / 4 per warp) -> no early
// returns, __syncwarp() is safe.
// ---------------------------------------------------------------------------
__global__ __launch_bounds__(256) void aggregate_kernel(const float4* __restrict__ bias4,
                                                        float* __restrict__ out) {
    int gwarp = (blockIdx.x * 256 + threadIdx.x) >> 5;
    int lane  = threadIdx.x & 31;
    int node  = gwarp * 4 + (lane >> 3);     // 4 nodes per warp, always < N_NODES
    int g = lane & 7;                        // col group of 8 halves

    int cnt = g_degs[N_NODES + node];
    const int* ep = &g_esrc[(size_t)node * ROW_CAP];

    float a0 = 0.f, a1 = 0.f, a2 = 0.f, a3 = 0.f;
    float a4 = 0.f, a5 = 0.f, a6 = 0.f, a7 = 0.f;

    int j = 0;
    for (; j + 8 <= cnt; j += 8) {
        uint4 r[8];
        #pragma unroll
        for (int q = 0; q < 8; q++) {
            int s = __ldcs(&ep[j + q]);
            r[q] = *(const uint4*)&g_h16[(size_t)s * OUT_C + g * 8];
        }
        // pairwise fp16 adds: (0+1),(2+3),(4+5),(6+7)
        #pragma unroll
        for (int p = 0; p < 4; p++) {
            __half2* hA = (__half2*)&r[2 * p];
            __half2* hB = (__half2*)&r[2 * p + 1];
            __half2 s0 = __hadd2(hA[0], hB[0]);
            __half2 s1 = __hadd2(hA[1], hB[1]);
            __half2 s2 = __hadd2(hA[2], hB[2]);
            __half2 s3 = __hadd2(hA[3], hB[3]);
            float2 f0 = __half22float2(s0);
            float2 f1 = __half22float2(s1);
            float2 f2 = __half22float2(s2);
            float2 f3 = __half22float2(s3);
            a0 += f0.x; a1 += f0.y; a2 += f1.x; a3 += f1.y;
            a4 += f2.x; a5 += f2.y; a6 += f3.x; a7 += f3.y;
        }
    }
    for (; j < cnt; j++) {
        int s = __ldcs(&ep[j]);
        uint4 r = *(const uint4*)&g_h16[(size_t)s * OUT_C + g * 8];
        float2 f0 = __half22float2(*(__half2*)&r.x);
        float2 f1 = __half22float2(*(__half2*)&r.y);
        float2 f2 = __half22float2(*(__half2*)&r.z);
        float2 f3 = __half22float2(*(__half2*)&r.w);
        a0 += f0.x; a1 += f0.y; a2 += f1.x; a3 += f1.y;
        a4 += f2.x; a5 += f2.y; a6 += f3.x; a7 += f3.y;
    }

    float rn = rsqrtf(fmaxf((float)cnt, 1.0f));
    float4 b0 = bias4[g * 2];
    float4 b1 = bias4[g * 2 + 1];
    float4 r0, r1;
    r0.x = a0 * rn + b0.x; r0.y = a1 * rn + b0.y;
    r0.z = a2 * rn + b0.z; r0.w = a3 * rn + b0.w;
    r1.x = a4 * rn + b1.x; r1.y = a5 * rn + b1.y;
    r1.z = a6 * rn + b1.z; r1.w = a7 * rn + b1.w;
    float* op = &out[(size_t)node * OUT_C + g * 8];
    __stcs((float4*)op, r0);
    __stcs((float4*)(op + 4), r1);

    // reset degree counters for the next graph replay (all reads done above)
    __syncwarp();
    if (g == 0) {
        g_degs[node] = 0;
        g_degs[N_NODES + node] = 0;
    }
}

// ---------------------------------------------------------------------------
extern "C" void kernel_launch(void* const* d_in, const int* in_sizes, int n_in,
                              void* d_out, int out_size) {
    const float* x      = (const float*)d_in[0];
    const float* weight = (const float*)d_in[1];
    const float* bias   = (const float*)d_in[2];
    const int*   src    = (const int*)d_in[3];
    const int*   dst    = (const int*)d_in[4];
    float* out = (float*)d_out;

    cudaStream_t s2;
    cudaEvent_t evFork, evFill;
    cudaStreamCreateWithFlags(&s2, cudaStreamNonBlocking);
    cudaEventCreateWithFlags(&evFork, cudaEventDisableTiming);
    cudaEventCreateWithFlags(&evFill, cudaEventDisableTiming);

    // fork from the origin (capture) stream FIRST
    cudaEventRecord(evFork, 0);
    cudaStreamWaitEvent(s2, evFork, 0);

    // ---- track B (s2): fused count+fill (padded CSR); counters pre-zeroed
    csr_fill_fused_kernel<<<(N_EDGES + 255) / 256, 256, 0, s2>>>(src, dst);
    cudaEventRecord(evFill, s2);

    // ---- track A (main): deg_out -> HMMA gemm (epilogue scales by norm_src)
    degree_out_kernel<<<(N_EDGES + 255) / 256, 256>>>(src);
    mma_gemm_kernel<<<(N_NODES + 127) / 128, 256>>>(x, weight);

    // join: aggregate needs h (main) + padded CSR (s2); resets counters
    cudaStreamWaitEvent(0, evFill, 0);
    int nwarps = (N_NODES + 3) / 4;
    aggregate_kernel<<<(nwarps + 7) / 8, 256>>>((const float4*)bias, out);

    cudaEventDestroy(evFork);
    cudaEventDestroy(evFill);
    cudaStreamDestroy(s2);
}